// round 12
// baseline (speedup 1.0000x reference)
#include <cuda_runtime.h>
#include <cuda_bf16.h>
#include <cstdint>
#include <cstddef>

// Problem constants
#define N_NODES 100000
#define E_MAX   1600000
#define F_IN    128
#define H_DIM   256
#define EMB_D   128
#define B_GR    1024
#define G_GRP   8
#define FAM_C   100

// ---------------- static device scratch (no allocs allowed) ----------------
__device__ __align__(16) int   g_counts[N_NODES];
__device__ __align__(16) int   g_rowptr[N_NODES];
__device__ __align__(16) int   g_cursor[N_NODES];
__device__ __align__(16) int   g_srcs[E_MAX];
__device__ __align__(16) int   g_bsums[1024];
__device__ __align__(16) float g_dinv[N_NODES];
__device__ __align__(16) __nv_bfloat16 g_a_h[(size_t)N_NODES * F_IN];   // agg1 hi
__device__ __align__(16) __nv_bfloat16 g_a_l[(size_t)N_NODES * F_IN];   // agg1 lo
__device__ __align__(16) __nv_bfloat16 g_h1h[(size_t)N_NODES * H_DIM];  // h1 hi
__device__ __align__(16) __nv_bfloat16 g_h1l[(size_t)N_NODES * H_DIM];  // h1 lo
__device__ __align__(16) float g_hw2[(size_t)N_NODES * EMB_D];          // h1 @ W2 (fp32)
__device__ __align__(16) __nv_bfloat16 g_w1h[H_DIM * F_IN];  // W1^T hi [N=256][K=128]
__device__ __align__(16) __nv_bfloat16 g_w1l[H_DIM * F_IN];
__device__ __align__(16) __nv_bfloat16 g_w2h[EMB_D * H_DIM]; // W2^T hi [N=128][K=256]
__device__ __align__(16) __nv_bfloat16 g_w2l[EMB_D * H_DIM];
__device__ __align__(16) float g_pool[(size_t)B_GR * EMB_D + B_GR];     // pool + cnt

static __device__ __forceinline__ uint32_t pack_bf2(__nv_bfloat16 a, __nv_bfloat16 b) {
    return (uint32_t)__bfloat16_as_ushort(a) | ((uint32_t)__bfloat16_as_ushort(b) << 16);
}

// m16n8k16 bf16 MMA, fp32 accumulate (portable: sm_80+, assembles for sm_103)
#define MMA_BF16(C, A0, A1, A2, A3, B0, B1) \
    asm volatile("mma.sync.aligned.m16n8k16.row.col.f32.bf16.bf16.f32 " \
                 "{%0,%1,%2,%3}, {%4,%5,%6,%7}, {%8,%9}, {%0,%1,%2,%3};" \
                 : "+f"((C)[0]), "+f"((C)[1]), "+f"((C)[2]), "+f"((C)[3]) \
                 : "r"(A0), "r"(A1), "r"(A2), "r"(A3), "r"(B0), "r"(B1))

// ---------------- small utility kernels ----------------
__global__ void fill0f4_kernel(float4* __restrict__ p, int n4) {
    int i = blockIdx.x * blockDim.x + threadIdx.x;
    if (i < n4) p[i] = make_float4(0.f, 0.f, 0.f, 0.f);
}

__global__ void zero_int_kernel(int* __restrict__ p, int n) {
    int i = blockIdx.x * blockDim.x + threadIdx.x;
    if (i < n) p[i] = 0;
}

// 4-wide vectorized degree histogram
__global__ void hist_kernel(const int* __restrict__ dst, int* __restrict__ counts, int e) {
    int i = blockIdx.x * blockDim.x + threadIdx.x;
    int i4 = i * 4;
    if (i4 + 3 < e) {
        int4 d = __ldg(reinterpret_cast<const int4*>(dst) + i);
        atomicAdd(counts + d.x, 1);
        atomicAdd(counts + d.y, 1);
        atomicAdd(counts + d.z, 1);
        atomicAdd(counts + d.w, 1);
    } else {
        for (int j = i4; j < e; j++) atomicAdd(counts + __ldg(dst + j), 1);
    }
}

// transpose + hi/lo split of weights: W[K][Nn] -> T{h,l}[Nn][K]
__global__ void wsplit_kernel(const float* __restrict__ W, __nv_bfloat16* __restrict__ Th,
                              __nv_bfloat16* __restrict__ Tl, int K, int Nn) {
    int i = blockIdx.x * blockDim.x + threadIdx.x;
    if (i >= K * Nn) return;
    int k = i / Nn, nn = i - k * Nn;
    float v = W[i];
    __nv_bfloat16 h = __float2bfloat16(v);
    float l = v - __bfloat162float(h);
    Th[(size_t)nn * K + k] = h;
    Tl[(size_t)nn * K + k] = __float2bfloat16(l);
}

// ---------------- 3-step exclusive scan of counts -> rowptr (+ dinv) -------
__global__ __launch_bounds__(1024)
void scan_block_kernel(const int* __restrict__ counts, int* __restrict__ rp,
                       int* __restrict__ bsums, float* __restrict__ dinv, int n)
{
    __shared__ int sh[1024];
    const int tid = threadIdx.x;
    const int i = blockIdx.x * 1024 + tid;
    int v = (i < n) ? counts[i] : 0;
    if (i < n) dinv[i] = rsqrtf((float)(v + 1));   // +1 self loop
    sh[tid] = v;
    __syncthreads();
#pragma unroll
    for (int off = 1; off < 1024; off <<= 1) {
        int t = 0;
        if (tid >= off) t = sh[tid - off];
        __syncthreads();
        if (tid >= off) sh[tid] += t;
        __syncthreads();
    }
    if (i < n) rp[i] = sh[tid] - v;
    if (tid == 1023) bsums[blockIdx.x] = sh[1023];
}

// parallel exclusive scan of block sums (nb <= 1024)
__global__ __launch_bounds__(1024)
void scan_sums_kernel(int* __restrict__ bsums, int nb) {
    __shared__ int sh[1024];
    const int tid = threadIdx.x;
    int v = (tid < nb) ? bsums[tid] : 0;
    sh[tid] = v;
    __syncthreads();
#pragma unroll
    for (int off = 1; off < 1024; off <<= 1) {
        int t = 0;
        if (tid >= off) t = sh[tid - off];
        __syncthreads();
        if (tid >= off) sh[tid] += t;
        __syncthreads();
    }
    if (tid < nb) bsums[tid] = sh[tid] - v;   // exclusive
}

__global__ __launch_bounds__(1024)
void scan_add_kernel(int* __restrict__ rp, int* __restrict__ cursor,
                     const int* __restrict__ bsums, int n)
{
    int i = blockIdx.x * 1024 + threadIdx.x;
    if (i < n) {
        int v = rp[i] + bsums[blockIdx.x];
        rp[i] = v;
        cursor[i] = v;
    }
}

// 4-wide vectorized CSR placement
__global__ void place_kernel(const int* __restrict__ src, const int* __restrict__ dst,
                             int* __restrict__ cursor, int* __restrict__ srcs, int e)
{
    int i = blockIdx.x * blockDim.x + threadIdx.x;
    int i4 = i * 4;
    if (i4 + 3 < e) {
        int4 d = __ldg(reinterpret_cast<const int4*>(dst) + i);
        int4 s = __ldg(reinterpret_cast<const int4*>(src) + i);
        srcs[atomicAdd(cursor + d.x, 1)] = s.x;
        srcs[atomicAdd(cursor + d.y, 1)] = s.y;
        srcs[atomicAdd(cursor + d.z, 1)] = s.z;
        srcs[atomicAdd(cursor + d.w, 1)] = s.w;
    } else {
        for (int j = i4; j < e; j++) {
            int d = __ldg(dst + j);
            srcs[atomicAdd(cursor + d, 1)] = __ldg(src + j);
        }
    }
}

// ---------------- CSR gather (layer 1) -> bf16 hi/lo split output ----------
__global__ __launch_bounds__(256)
void gather_split_kernel(const float* __restrict__ in,
                         __nv_bfloat16* __restrict__ oh, __nv_bfloat16* __restrict__ ol,
                         const int* __restrict__ rowptr, const int* __restrict__ counts,
                         const int* __restrict__ srcs, const float* __restrict__ dinv,
                         int n)
{
    const int w = (blockIdx.x * 256 + threadIdx.x) >> 5;
    const int lane = threadIdx.x & 31;
    if (w >= n) return;

    const int beg = __ldg(rowptr + w);
    const int deg = __ldg(counts + w);
    const float dw = __ldg(dinv + w);

    float4 acc = __ldg(reinterpret_cast<const float4*>(in + (size_t)w * 128) + lane);
    acc.x *= dw; acc.y *= dw; acc.z *= dw; acc.w *= dw;

    int i = 0;
    for (; i + 4 <= deg; i += 4) {
        int s0 = __ldg(srcs + beg + i);
        int s1 = __ldg(srcs + beg + i + 1);
        int s2 = __ldg(srcs + beg + i + 2);
        int s3 = __ldg(srcs + beg + i + 3);
        float d0 = __ldg(dinv + s0), d1 = __ldg(dinv + s1);
        float d2 = __ldg(dinv + s2), d3 = __ldg(dinv + s3);
        float4 v0 = __ldg(reinterpret_cast<const float4*>(in + (size_t)s0 * 128) + lane);
        float4 v1 = __ldg(reinterpret_cast<const float4*>(in + (size_t)s1 * 128) + lane);
        float4 v2 = __ldg(reinterpret_cast<const float4*>(in + (size_t)s2 * 128) + lane);
        float4 v3 = __ldg(reinterpret_cast<const float4*>(in + (size_t)s3 * 128) + lane);
        acc.x = fmaf(v0.x, d0, acc.x); acc.y = fmaf(v0.y, d0, acc.y);
        acc.z = fmaf(v0.z, d0, acc.z); acc.w = fmaf(v0.w, d0, acc.w);
        acc.x = fmaf(v1.x, d1, acc.x); acc.y = fmaf(v1.y, d1, acc.y);
        acc.z = fmaf(v1.z, d1, acc.z); acc.w = fmaf(v1.w, d1, acc.w);
        acc.x = fmaf(v2.x, d2, acc.x); acc.y = fmaf(v2.y, d2, acc.y);
        acc.z = fmaf(v2.z, d2, acc.z); acc.w = fmaf(v2.w, d2, acc.w);
        acc.x = fmaf(v3.x, d3, acc.x); acc.y = fmaf(v3.y, d3, acc.y);
        acc.z = fmaf(v3.z, d3, acc.z); acc.w = fmaf(v3.w, d3, acc.w);
    }
    for (; i < deg; i++) {
        int s = __ldg(srcs + beg + i);
        float ds = __ldg(dinv + s);
        float4 v = __ldg(reinterpret_cast<const float4*>(in + (size_t)s * 128) + lane);
        acc.x = fmaf(v.x, ds, acc.x); acc.y = fmaf(v.y, ds, acc.y);
        acc.z = fmaf(v.z, ds, acc.z); acc.w = fmaf(v.w, ds, acc.w);
    }
    acc.x *= dw; acc.y *= dw; acc.z *= dw; acc.w *= dw;

    __nv_bfloat16 hx = __float2bfloat16(acc.x), hy = __float2bfloat16(acc.y);
    __nv_bfloat16 hz = __float2bfloat16(acc.z), hw2 = __float2bfloat16(acc.w);
    float lx = acc.x - __bfloat162float(hx), ly = acc.y - __bfloat162float(hy);
    float lz = acc.z - __bfloat162float(hz), lw = acc.w - __bfloat162float(hw2);
    uint2 hv, lv;
    hv.x = pack_bf2(hx, hy); hv.y = pack_bf2(hz, hw2);
    lv.x = pack_bf2(__float2bfloat16(lx), __float2bfloat16(ly));
    lv.y = pack_bf2(__float2bfloat16(lz), __float2bfloat16(lw));
    reinterpret_cast<uint2*>(oh + (size_t)w * 128)[lane] = hv;
    reinterpret_cast<uint2*>(ol + (size_t)w * 128)[lane] = lv;
}

// ---------------- fused layer-2 gather + mean-pool accumulation ----------------
__global__ __launch_bounds__(256)
void gather_pool_kernel(const float* __restrict__ in,
                        const int* __restrict__ rowptr, const int* __restrict__ counts,
                        const int* __restrict__ srcs, const float* __restrict__ dinv,
                        const int* __restrict__ batch,
                        float* __restrict__ pool, float* __restrict__ cnt, int n)
{
    const int w = (blockIdx.x * 256 + threadIdx.x) >> 5;
    const int lane = threadIdx.x & 31;
    if (w >= n) return;

    const int beg = __ldg(rowptr + w);
    const int deg = __ldg(counts + w);
    const float dw = __ldg(dinv + w);
    const int b = __ldg(batch + w);

    float4 acc = __ldg(reinterpret_cast<const float4*>(in + (size_t)w * 128) + lane);
    acc.x *= dw; acc.y *= dw; acc.z *= dw; acc.w *= dw;

    int i = 0;
    for (; i + 4 <= deg; i += 4) {
        int s0 = __ldg(srcs + beg + i);
        int s1 = __ldg(srcs + beg + i + 1);
        int s2 = __ldg(srcs + beg + i + 2);
        int s3 = __ldg(srcs + beg + i + 3);
        float d0 = __ldg(dinv + s0), d1 = __ldg(dinv + s1);
        float d2 = __ldg(dinv + s2), d3 = __ldg(dinv + s3);
        float4 v0 = __ldg(reinterpret_cast<const float4*>(in + (size_t)s0 * 128) + lane);
        float4 v1 = __ldg(reinterpret_cast<const float4*>(in + (size_t)s1 * 128) + lane);
        float4 v2 = __ldg(reinterpret_cast<const float4*>(in + (size_t)s2 * 128) + lane);
        float4 v3 = __ldg(reinterpret_cast<const float4*>(in + (size_t)s3 * 128) + lane);
        acc.x = fmaf(v0.x, d0, acc.x); acc.y = fmaf(v0.y, d0, acc.y);
        acc.z = fmaf(v0.z, d0, acc.z); acc.w = fmaf(v0.w, d0, acc.w);
        acc.x = fmaf(v1.x, d1, acc.x); acc.y = fmaf(v1.y, d1, acc.y);
        acc.z = fmaf(v1.z, d1, acc.z); acc.w = fmaf(v1.w, d1, acc.w);
        acc.x = fmaf(v2.x, d2, acc.x); acc.y = fmaf(v2.y, d2, acc.y);
        acc.z = fmaf(v2.z, d2, acc.z); acc.w = fmaf(v2.w, d2, acc.w);
        acc.x = fmaf(v3.x, d3, acc.x); acc.y = fmaf(v3.y, d3, acc.y);
        acc.z = fmaf(v3.z, d3, acc.z); acc.w = fmaf(v3.w, d3, acc.w);
    }
    for (; i < deg; i++) {
        int s = __ldg(srcs + beg + i);
        float ds = __ldg(dinv + s);
        float4 v = __ldg(reinterpret_cast<const float4*>(in + (size_t)s * 128) + lane);
        acc.x = fmaf(v.x, ds, acc.x); acc.y = fmaf(v.y, ds, acc.y);
        acc.z = fmaf(v.z, ds, acc.z); acc.w = fmaf(v.w, ds, acc.w);
    }
    acc.x *= dw; acc.y *= dw; acc.z *= dw; acc.w *= dw;
    atomicAdd(reinterpret_cast<float4*>(pool + (size_t)b * 128) + lane, acc);
    if (lane == 0) atomicAdd(cnt + b, 1.0f);
}

// ---------------- mma.sync GEMM: C[128, 128] tile of A[M,K] @ Bt^T ----------
// A as bf16 hi/lo [M][K_TOT]; Bt as bf16 hi/lo [N][K_TOT] (row = output col).
// 3-pass compensated bf16: A_hi*B_hi + A_hi*B_lo + A_lo*B_hi, fp32 reg accum.
// 256 thr = 8 warps, warp tile 64x32 (2x4 warp grid), BK = 64.
// SPLIT_OUT: out = relu(C + bias) as bf16 hi/lo. Else: fp32 out.
#define LDS_B 72          // smem row stride in bf16 (144 bytes)
#define TILE_SM (128 * LDS_B * 2)   // 18432 bytes per 128x64 tile
#define GEMM_SMEM (512 + 4 * TILE_SM)

template<bool SPLIT_OUT>
__global__ __launch_bounds__(256, 2)
void gemm_mma_kernel(const __nv_bfloat16* __restrict__ Ah, const __nv_bfloat16* __restrict__ Al,
                     const __nv_bfloat16* __restrict__ Bh, const __nv_bfloat16* __restrict__ Bl,
                     const float* __restrict__ bias,
                     __nv_bfloat16* __restrict__ Oh, __nv_bfloat16* __restrict__ Ol,
                     float* __restrict__ Of,
                     int M, int K_TOT, int N_STRIDE)
{
    extern __shared__ __align__(16) char smem[];
    float* sbias = reinterpret_cast<float*>(smem);
    __nv_bfloat16* sAh = reinterpret_cast<__nv_bfloat16*>(smem + 512);
    __nv_bfloat16* sAl = reinterpret_cast<__nv_bfloat16*>(smem + 512 + TILE_SM);
    __nv_bfloat16* sBh = reinterpret_cast<__nv_bfloat16*>(smem + 512 + 2 * TILE_SM);
    __nv_bfloat16* sBl = reinterpret_cast<__nv_bfloat16*>(smem + 512 + 3 * TILE_SM);

    const int tid = threadIdx.x;
    const int wid = tid >> 5, lane = tid & 31;
    const int g = lane >> 2, tg = lane & 3;
    const int bm = blockIdx.x * 128;
    const int nybase = blockIdx.y * 128;
    const int wm = (wid & 1) * 64;       // warp M offset
    const int wn = (wid >> 1) * 32;      // warp N offset

    if (SPLIT_OUT && tid < 128) sbias[tid] = bias[nybase + tid];

    float c[4][4][4];
#pragma unroll
    for (int mi = 0; mi < 4; mi++)
#pragma unroll
        for (int nj = 0; nj < 4; nj++)
#pragma unroll
            for (int q = 0; q < 4; q++) c[mi][nj][q] = 0.f;

    for (int kc = 0; kc < K_TOT; kc += 64) {
        // ---- stage 128x64 chunks of Ah/Al/Bh/Bl into smem ----
#pragma unroll
        for (int it = 0; it < 4; it++) {
            int idx = tid + it * 256;           // 0..1023
            int row = idx >> 3, q = idx & 7;    // 8 uint4 per 64-bf16 row
            int m = bm + row; if (m >= M) m = M - 1;
            size_t ga = (size_t)m * K_TOT + kc;
            size_t gb = (size_t)(nybase + row) * K_TOT + kc;
            reinterpret_cast<uint4*>(sAh + row * LDS_B)[q] =
                reinterpret_cast<const uint4*>(Ah + ga)[q];
            reinterpret_cast<uint4*>(sAl + row * LDS_B)[q] =
                reinterpret_cast<const uint4*>(Al + ga)[q];
            reinterpret_cast<uint4*>(sBh + row * LDS_B)[q] =
                reinterpret_cast<const uint4*>(Bh + gb)[q];
            reinterpret_cast<uint4*>(sBl + row * LDS_B)[q] =
                reinterpret_cast<const uint4*>(Bl + gb)[q];
        }
        __syncthreads();

#pragma unroll
        for (int ks = 0; ks < 4; ks++) {
            const int k0 = ks * 16;
            uint32_t fbh[4][2], fbl[4][2];
#pragma unroll
            for (int nj = 0; nj < 4; nj++) {
                const __nv_bfloat16* ph = sBh + (wn + nj * 8 + g) * LDS_B + k0 + tg * 2;
                fbh[nj][0] = *reinterpret_cast<const uint32_t*>(ph);
                fbh[nj][1] = *reinterpret_cast<const uint32_t*>(ph + 8);
                const __nv_bfloat16* pl = sBl + (wn + nj * 8 + g) * LDS_B + k0 + tg * 2;
                fbl[nj][0] = *reinterpret_cast<const uint32_t*>(pl);
                fbl[nj][1] = *reinterpret_cast<const uint32_t*>(pl + 8);
            }
#pragma unroll
            for (int mi = 0; mi < 4; mi++) {
                const __nv_bfloat16* pah = sAh + (wm + mi * 16 + g) * LDS_B + k0 + tg * 2;
                uint32_t ah0 = *reinterpret_cast<const uint32_t*>(pah);
                uint32_t ah1 = *reinterpret_cast<const uint32_t*>(pah + 8 * LDS_B);
                uint32_t ah2 = *reinterpret_cast<const uint32_t*>(pah + 8);
                uint32_t ah3 = *reinterpret_cast<const uint32_t*>(pah + 8 * LDS_B + 8);
                const __nv_bfloat16* pal = sAl + (wm + mi * 16 + g) * LDS_B + k0 + tg * 2;
                uint32_t al0 = *reinterpret_cast<const uint32_t*>(pal);
                uint32_t al1 = *reinterpret_cast<const uint32_t*>(pal + 8 * LDS_B);
                uint32_t al2 = *reinterpret_cast<const uint32_t*>(pal + 8);
                uint32_t al3 = *reinterpret_cast<const uint32_t*>(pal + 8 * LDS_B + 8);
#pragma unroll
                for (int nj = 0; nj < 4; nj++) {
                    MMA_BF16(c[mi][nj], ah0, ah1, ah2, ah3, fbh[nj][0], fbh[nj][1]);
                    MMA_BF16(c[mi][nj], ah0, ah1, ah2, ah3, fbl[nj][0], fbl[nj][1]);
                    MMA_BF16(c[mi][nj], al0, al1, al2, al3, fbh[nj][0], fbh[nj][1]);
                }
            }
        }
        __syncthreads();
    }

    // ---- epilogue ----
#pragma unroll
    for (int mi = 0; mi < 4; mi++) {
        const int r0 = bm + wm + mi * 16 + g;
        const int r1 = r0 + 8;
#pragma unroll
        for (int nj = 0; nj < 4; nj++) {
            const int col = wn + nj * 8 + tg * 2;   // local col (even)
            const int gc = nybase + col;
            float v0 = c[mi][nj][0], v1 = c[mi][nj][1];
            float v2 = c[mi][nj][2], v3 = c[mi][nj][3];
            if (SPLIT_OUT) {
                const float b0 = sbias[col], b1 = sbias[col + 1];
                v0 = fmaxf(v0 + b0, 0.f); v1 = fmaxf(v1 + b1, 0.f);
                v2 = fmaxf(v2 + b0, 0.f); v3 = fmaxf(v3 + b1, 0.f);
                __nv_bfloat16 h0 = __float2bfloat16(v0), h1 = __float2bfloat16(v1);
                __nv_bfloat16 h2 = __float2bfloat16(v2), h3 = __float2bfloat16(v3);
                float l0 = v0 - __bfloat162float(h0), l1 = v1 - __bfloat162float(h1);
                float l2 = v2 - __bfloat162float(h2), l3 = v3 - __bfloat162float(h3);
                if (r0 < M) {
                    *reinterpret_cast<uint32_t*>(Oh + (size_t)r0 * N_STRIDE + gc) = pack_bf2(h0, h1);
                    *reinterpret_cast<uint32_t*>(Ol + (size_t)r0 * N_STRIDE + gc) =
                        pack_bf2(__float2bfloat16(l0), __float2bfloat16(l1));
                }
                if (r1 < M) {
                    *reinterpret_cast<uint32_t*>(Oh + (size_t)r1 * N_STRIDE + gc) = pack_bf2(h2, h3);
                    *reinterpret_cast<uint32_t*>(Ol + (size_t)r1 * N_STRIDE + gc) =
                        pack_bf2(__float2bfloat16(l2), __float2bfloat16(l3));
                }
            } else {
                if (r0 < M)
                    *reinterpret_cast<float2*>(Of + (size_t)r0 * N_STRIDE + gc) = make_float2(v0, v1);
                if (r1 < M)
                    *reinterpret_cast<float2*>(Of + (size_t)r1 * N_STRIDE + gc) = make_float2(v2, v3);
            }
        }
    }
}

// ---------------- head: emb, group logits, argmax, family logits -----------
__global__ __launch_bounds__(128)
void head_kernel(const float* __restrict__ b2, const float* __restrict__ Wg,
                 const float* __restrict__ bg, const float* __restrict__ Wf,
                 const float* __restrict__ bf,
                 const float* __restrict__ pool, const float* __restrict__ cnt,
                 float* __restrict__ out_emb, float* __restrict__ out_gl,
                 float* __restrict__ out_fam)
{
    const int b = blockIdx.x;
    const int t = threadIdx.x;
    __shared__ float s_emb[EMB_D];
    __shared__ float s_lg[G_GRP];
    __shared__ int s_grp;

    float c = cnt[b];
    float e = 0.f;
    if (c > 0.f) e = pool[(size_t)b * EMB_D + t] / c + b2[t];
    out_emb[(size_t)b * EMB_D + t] = e;
    s_emb[t] = e;
    __syncthreads();

    if (t < G_GRP) {
        float lg = bg[t];
#pragma unroll 8
        for (int k = 0; k < EMB_D; k++)
            lg = fmaf(s_emb[k], Wg[k * G_GRP + t], lg);
        out_gl[(size_t)b * G_GRP + t] = lg;
        s_lg[t] = lg;
    }
    __syncthreads();

    if (t == 0) {
        int gm = 0; float m = s_lg[0];
#pragma unroll
        for (int j = 1; j < G_GRP; j++)
            if (s_lg[j] > m) { m = s_lg[j]; gm = j; }
        s_grp = gm;
    }
    __syncthreads();

    const int g = s_grp;
    if (t < FAM_C) {
        float v = bf[g * FAM_C + t];
        const float* wf = Wf + (size_t)g * EMB_D * FAM_C + t;
#pragma unroll 8
        for (int k = 0; k < EMB_D; k++)
            v = fmaf(s_emb[k], wf[(size_t)k * FAM_C], v);
        out_fam[((size_t)g * B_GR + b) * FAM_C + t] = v;
    }
}

// ---------------- launch ----------------
extern "C" void kernel_launch(void* const* d_in, const int* in_sizes, int n_in,
                              void* d_out, int out_size)
{
    const float* x    = (const float*)d_in[0];
    const float* W1   = (const float*)d_in[1];
    const float* b1   = (const float*)d_in[2];
    const float* W2   = (const float*)d_in[3];
    const float* b2   = (const float*)d_in[4];
    const float* Wg   = (const float*)d_in[5];
    const float* bg   = (const float*)d_in[6];
    const float* Wf   = (const float*)d_in[7];
    const float* bf   = (const float*)d_in[8];
    const int*   edge = (const int*)d_in[9];
    const int*   batch= (const int*)d_in[10];

    const int E = in_sizes[9] / 2;
    const int n = in_sizes[10];
    const int nb = (n + 1023) / 1024;

    int *counts, *rowptr, *cursor, *srcs, *bsums;
    float *dinv, *hw2, *poolcnt;
    __nv_bfloat16 *ah, *al, *h1h, *h1l, *w1h, *w1l, *w2h, *w2l;
    cudaGetSymbolAddress((void**)&counts, g_counts);
    cudaGetSymbolAddress((void**)&rowptr, g_rowptr);
    cudaGetSymbolAddress((void**)&cursor, g_cursor);
    cudaGetSymbolAddress((void**)&srcs,   g_srcs);
    cudaGetSymbolAddress((void**)&bsums,  g_bsums);
    cudaGetSymbolAddress((void**)&dinv,   g_dinv);
    cudaGetSymbolAddress((void**)&ah,     g_a_h);
    cudaGetSymbolAddress((void**)&al,     g_a_l);
    cudaGetSymbolAddress((void**)&h1h,    g_h1h);
    cudaGetSymbolAddress((void**)&h1l,    g_h1l);
    cudaGetSymbolAddress((void**)&hw2,    g_hw2);
    cudaGetSymbolAddress((void**)&w1h,    g_w1h);
    cudaGetSymbolAddress((void**)&w1l,    g_w1l);
    cudaGetSymbolAddress((void**)&w2h,    g_w2h);
    cudaGetSymbolAddress((void**)&w2l,    g_w2l);
    cudaGetSymbolAddress((void**)&poolcnt,g_pool);
    float* pool = poolcnt;
    float* cnt  = poolcnt + (size_t)B_GR * EMB_D;

    float* out = (float*)d_out;
    float* out_emb = out;
    float* out_gl  = out + (size_t)B_GR * EMB_D;
    float* out_fam = out_gl + (size_t)B_GR * G_GRP;

    const int* src = edge;
    const int* dst = edge + E;

    cudaFuncSetAttribute(gemm_mma_kernel<true>,
                         cudaFuncAttributeMaxDynamicSharedMemorySize, GEMM_SMEM);
    cudaFuncSetAttribute(gemm_mma_kernel<false>,
                         cudaFuncAttributeMaxDynamicSharedMemorySize, GEMM_SMEM);

    // ---- CSR build ----
    zero_int_kernel<<<(n + 255) / 256, 256>>>(counts, n);
    hist_kernel<<<(E / 4 + 255) / 256, 256>>>(dst, counts, E);
    scan_block_kernel<<<nb, 1024>>>(counts, rowptr, bsums, dinv, n);
    scan_sums_kernel<<<1, 1024>>>(bsums, nb);
    scan_add_kernel<<<nb, 1024>>>(rowptr, cursor, bsums, n);
    place_kernel<<<(E / 4 + 255) / 256, 256>>>(src, dst, cursor, srcs, E);

    // ---- weight transpose + split (tiny) ----
    wsplit_kernel<<<(F_IN * H_DIM + 255) / 256, 256>>>(W1, w1h, w1l, F_IN, H_DIM);
    wsplit_kernel<<<(H_DIM * EMB_D + 255) / 256, 256>>>(W2, w2h, w2l, H_DIM, EMB_D);

    // ---- layer 1: gather (fp32 acc -> bf16 hi/lo), then HMMA GEMM ----
    gather_split_kernel<<<(n + 7) / 8, 256>>>(x, ah, al, rowptr, counts, srcs, dinv, n);
    {
        dim3 grid((n + 127) / 128, 2);   // N = 256
        gemm_mma_kernel<true><<<grid, 256, GEMM_SMEM>>>(
            ah, al, w1h, w1l, b1, h1h, h1l, nullptr, n, F_IN, H_DIM);
    }

    // ---- layer 2: HMMA GEMM (fp32 out), then fused gather+pool ----
    {
        dim3 grid((n + 127) / 128, 1);   // N = 128, K = 256
        gemm_mma_kernel<false><<<grid, 256, GEMM_SMEM>>>(
            h1h, h1l, w2h, w2l, nullptr, nullptr, nullptr, hw2, n, H_DIM, EMB_D);
    }
    {
        int n4 = (B_GR * EMB_D + B_GR) / 4;
        fill0f4_kernel<<<(n4 + 255) / 256, 256>>>((float4*)poolcnt, n4);
    }
    gather_pool_kernel<<<(n + 7) / 8, 256>>>(hw2, rowptr, counts, srcs, dinv,
                                             batch, pool, cnt, n);

    // ---- heads ----
    {
        int n4 = (G_GRP * B_GR * FAM_C) / 4;
        fill0f4_kernel<<<(n4 + 255) / 256, 256>>>((float4*)out_fam, n4);
    }
    head_kernel<<<B_GR, 128>>>(b2, Wg, bg, Wf, bf, pool, cnt,
                               out_emb, out_gl, out_fam);
}

// round 13
// speedup vs baseline: 1.0039x; 1.0039x over previous
#include <cuda_runtime.h>
#include <cuda_bf16.h>
#include <cstdint>
#include <cstddef>

// Problem constants
#define N_NODES 100000
#define E_MAX   1600000
#define F_IN    128
#define H_DIM   256
#define EMB_D   128
#define B_GR    1024
#define G_GRP   8
#define FAM_C   100

// ---------------- static device scratch (no allocs allowed) ----------------
__device__ __align__(16) int   g_counts[N_NODES];
__device__ __align__(16) int   g_rowptr[N_NODES];
__device__ __align__(16) int   g_cursor[N_NODES];
__device__ __align__(16) int   g_srcs[E_MAX];
__device__ __align__(16) int   g_bsums[1024];
__device__ __align__(16) float g_dinv[N_NODES];
__device__ __align__(16) __nv_bfloat16 g_a_h[(size_t)N_NODES * F_IN];   // agg1 hi
__device__ __align__(16) __nv_bfloat16 g_a_l[(size_t)N_NODES * F_IN];   // agg1 lo
__device__ __align__(16) __nv_bfloat16 g_h1h[(size_t)N_NODES * H_DIM];  // h1 hi
__device__ __align__(16) __nv_bfloat16 g_h1l[(size_t)N_NODES * H_DIM];  // h1 lo
__device__ __align__(16) float g_hw2[(size_t)N_NODES * EMB_D];          // h1 @ W2 (fp32)
__device__ __align__(16) __nv_bfloat16 g_w1h[H_DIM * F_IN];  // W1^T hi [N=256][K=128]
__device__ __align__(16) __nv_bfloat16 g_w1l[H_DIM * F_IN];
__device__ __align__(16) __nv_bfloat16 g_w2h[EMB_D * H_DIM]; // W2^T hi [N=128][K=256]
__device__ __align__(16) __nv_bfloat16 g_w2l[EMB_D * H_DIM];
__device__ __align__(16) float g_pool[(size_t)B_GR * EMB_D + B_GR];     // pool + cnt

static __device__ __forceinline__ uint32_t pack_bf2(__nv_bfloat16 a, __nv_bfloat16 b) {
    return (uint32_t)__bfloat16_as_ushort(a) | ((uint32_t)__bfloat16_as_ushort(b) << 16);
}

// m16n8k16 bf16 MMA, fp32 accumulate (portable: sm_80+, assembles for sm_103)
#define MMA_BF16(C, A0, A1, A2, A3, B0, B1) \
    asm volatile("mma.sync.aligned.m16n8k16.row.col.f32.bf16.bf16.f32 " \
                 "{%0,%1,%2,%3}, {%4,%5,%6,%7}, {%8,%9}, {%0,%1,%2,%3};" \
                 : "+f"((C)[0]), "+f"((C)[1]), "+f"((C)[2]), "+f"((C)[3]) \
                 : "r"(A0), "r"(A1), "r"(A2), "r"(A3), "r"(B0), "r"(B1))

// ---------------- small utility kernels ----------------
__global__ void fill0f4_kernel(float4* __restrict__ p, int n4) {
    int i = blockIdx.x * blockDim.x + threadIdx.x;
    if (i < n4) p[i] = make_float4(0.f, 0.f, 0.f, 0.f);
}

__global__ void zero_int_kernel(int* __restrict__ p, int n) {
    int i = blockIdx.x * blockDim.x + threadIdx.x;
    if (i < n) p[i] = 0;
}

// 4-wide vectorized degree histogram
__global__ void hist_kernel(const int* __restrict__ dst, int* __restrict__ counts, int e) {
    int i = blockIdx.x * blockDim.x + threadIdx.x;
    int i4 = i * 4;
    if (i4 + 3 < e) {
        int4 d = __ldg(reinterpret_cast<const int4*>(dst) + i);
        atomicAdd(counts + d.x, 1);
        atomicAdd(counts + d.y, 1);
        atomicAdd(counts + d.z, 1);
        atomicAdd(counts + d.w, 1);
    } else {
        for (int j = i4; j < e; j++) atomicAdd(counts + __ldg(dst + j), 1);
    }
}

// transpose + hi/lo split of weights: W[K][Nn] -> T{h,l}[Nn][K]
__global__ void wsplit_kernel(const float* __restrict__ W, __nv_bfloat16* __restrict__ Th,
                              __nv_bfloat16* __restrict__ Tl, int K, int Nn) {
    int i = blockIdx.x * blockDim.x + threadIdx.x;
    if (i >= K * Nn) return;
    int k = i / Nn, nn = i - k * Nn;
    float v = W[i];
    __nv_bfloat16 h = __float2bfloat16(v);
    float l = v - __bfloat162float(h);
    Th[(size_t)nn * K + k] = h;
    Tl[(size_t)nn * K + k] = __float2bfloat16(l);
}

// ---------------- 3-step exclusive scan of counts -> rowptr (+ dinv) -------
__global__ __launch_bounds__(1024)
void scan_block_kernel(const int* __restrict__ counts, int* __restrict__ rp,
                       int* __restrict__ bsums, float* __restrict__ dinv, int n)
{
    __shared__ int sh[1024];
    const int tid = threadIdx.x;
    const int i = blockIdx.x * 1024 + tid;
    int v = (i < n) ? counts[i] : 0;
    if (i < n) dinv[i] = rsqrtf((float)(v + 1));   // +1 self loop
    sh[tid] = v;
    __syncthreads();
#pragma unroll
    for (int off = 1; off < 1024; off <<= 1) {
        int t = 0;
        if (tid >= off) t = sh[tid - off];
        __syncthreads();
        if (tid >= off) sh[tid] += t;
        __syncthreads();
    }
    if (i < n) rp[i] = sh[tid] - v;
    if (tid == 1023) bsums[blockIdx.x] = sh[1023];
}

// parallel exclusive scan of block sums (nb <= 1024)
__global__ __launch_bounds__(1024)
void scan_sums_kernel(int* __restrict__ bsums, int nb) {
    __shared__ int sh[1024];
    const int tid = threadIdx.x;
    int v = (tid < nb) ? bsums[tid] : 0;
    sh[tid] = v;
    __syncthreads();
#pragma unroll
    for (int off = 1; off < 1024; off <<= 1) {
        int t = 0;
        if (tid >= off) t = sh[tid - off];
        __syncthreads();
        if (tid >= off) sh[tid] += t;
        __syncthreads();
    }
    if (tid < nb) bsums[tid] = sh[tid] - v;   // exclusive
}

__global__ __launch_bounds__(1024)
void scan_add_kernel(int* __restrict__ rp, int* __restrict__ cursor,
                     const int* __restrict__ bsums, int n)
{
    int i = blockIdx.x * 1024 + threadIdx.x;
    if (i < n) {
        int v = rp[i] + bsums[blockIdx.x];
        rp[i] = v;
        cursor[i] = v;
    }
}

// 4-wide vectorized CSR placement
__global__ void place_kernel(const int* __restrict__ src, const int* __restrict__ dst,
                             int* __restrict__ cursor, int* __restrict__ srcs, int e)
{
    int i = blockIdx.x * blockDim.x + threadIdx.x;
    int i4 = i * 4;
    if (i4 + 3 < e) {
        int4 d = __ldg(reinterpret_cast<const int4*>(dst) + i);
        int4 s = __ldg(reinterpret_cast<const int4*>(src) + i);
        srcs[atomicAdd(cursor + d.x, 1)] = s.x;
        srcs[atomicAdd(cursor + d.y, 1)] = s.y;
        srcs[atomicAdd(cursor + d.z, 1)] = s.z;
        srcs[atomicAdd(cursor + d.w, 1)] = s.w;
    } else {
        for (int j = i4; j < e; j++) {
            int d = __ldg(dst + j);
            srcs[atomicAdd(cursor + d, 1)] = __ldg(src + j);
        }
    }
}

// ---------------- CSR gather (layer 1) -> bf16 hi/lo split output ----------
__global__ __launch_bounds__(256)
void gather_split_kernel(const float* __restrict__ in,
                         __nv_bfloat16* __restrict__ oh, __nv_bfloat16* __restrict__ ol,
                         const int* __restrict__ rowptr, const int* __restrict__ counts,
                         const int* __restrict__ srcs, const float* __restrict__ dinv,
                         int n)
{
    const int w = (blockIdx.x * 256 + threadIdx.x) >> 5;
    const int lane = threadIdx.x & 31;
    if (w >= n) return;

    const int beg = __ldg(rowptr + w);
    const int deg = __ldg(counts + w);
    const float dw = __ldg(dinv + w);

    float4 acc = __ldg(reinterpret_cast<const float4*>(in + (size_t)w * 128) + lane);
    acc.x *= dw; acc.y *= dw; acc.z *= dw; acc.w *= dw;

    int i = 0;
    for (; i + 4 <= deg; i += 4) {
        int s0 = __ldg(srcs + beg + i);
        int s1 = __ldg(srcs + beg + i + 1);
        int s2 = __ldg(srcs + beg + i + 2);
        int s3 = __ldg(srcs + beg + i + 3);
        float d0 = __ldg(dinv + s0), d1 = __ldg(dinv + s1);
        float d2 = __ldg(dinv + s2), d3 = __ldg(dinv + s3);
        float4 v0 = __ldg(reinterpret_cast<const float4*>(in + (size_t)s0 * 128) + lane);
        float4 v1 = __ldg(reinterpret_cast<const float4*>(in + (size_t)s1 * 128) + lane);
        float4 v2 = __ldg(reinterpret_cast<const float4*>(in + (size_t)s2 * 128) + lane);
        float4 v3 = __ldg(reinterpret_cast<const float4*>(in + (size_t)s3 * 128) + lane);
        acc.x = fmaf(v0.x, d0, acc.x); acc.y = fmaf(v0.y, d0, acc.y);
        acc.z = fmaf(v0.z, d0, acc.z); acc.w = fmaf(v0.w, d0, acc.w);
        acc.x = fmaf(v1.x, d1, acc.x); acc.y = fmaf(v1.y, d1, acc.y);
        acc.z = fmaf(v1.z, d1, acc.z); acc.w = fmaf(v1.w, d1, acc.w);
        acc.x = fmaf(v2.x, d2, acc.x); acc.y = fmaf(v2.y, d2, acc.y);
        acc.z = fmaf(v2.z, d2, acc.z); acc.w = fmaf(v2.w, d2, acc.w);
        acc.x = fmaf(v3.x, d3, acc.x); acc.y = fmaf(v3.y, d3, acc.y);
        acc.z = fmaf(v3.z, d3, acc.z); acc.w = fmaf(v3.w, d3, acc.w);
    }
    for (; i < deg; i++) {
        int s = __ldg(srcs + beg + i);
        float ds = __ldg(dinv + s);
        float4 v = __ldg(reinterpret_cast<const float4*>(in + (size_t)s * 128) + lane);
        acc.x = fmaf(v.x, ds, acc.x); acc.y = fmaf(v.y, ds, acc.y);
        acc.z = fmaf(v.z, ds, acc.z); acc.w = fmaf(v.w, ds, acc.w);
    }
    acc.x *= dw; acc.y *= dw; acc.z *= dw; acc.w *= dw;

    __nv_bfloat16 hx = __float2bfloat16(acc.x), hy = __float2bfloat16(acc.y);
    __nv_bfloat16 hz = __float2bfloat16(acc.z), hw2 = __float2bfloat16(acc.w);
    float lx = acc.x - __bfloat162float(hx), ly = acc.y - __bfloat162float(hy);
    float lz = acc.z - __bfloat162float(hz), lw = acc.w - __bfloat162float(hw2);
    uint2 hv, lv;
    hv.x = pack_bf2(hx, hy); hv.y = pack_bf2(hz, hw2);
    lv.x = pack_bf2(__float2bfloat16(lx), __float2bfloat16(ly));
    lv.y = pack_bf2(__float2bfloat16(lz), __float2bfloat16(lw));
    reinterpret_cast<uint2*>(oh + (size_t)w * 128)[lane] = hv;
    reinterpret_cast<uint2*>(ol + (size_t)w * 128)[lane] = lv;
}

// ---------------- fused layer-2 gather + mean-pool accumulation ----------------
__global__ __launch_bounds__(256)
void gather_pool_kernel(const float* __restrict__ in,
                        const int* __restrict__ rowptr, const int* __restrict__ counts,
                        const int* __restrict__ srcs, const float* __restrict__ dinv,
                        const int* __restrict__ batch,
                        float* __restrict__ pool, float* __restrict__ cnt, int n)
{
    const int w = (blockIdx.x * 256 + threadIdx.x) >> 5;
    const int lane = threadIdx.x & 31;
    if (w >= n) return;

    const int beg = __ldg(rowptr + w);
    const int deg = __ldg(counts + w);
    const float dw = __ldg(dinv + w);
    const int b = __ldg(batch + w);

    float4 acc = __ldg(reinterpret_cast<const float4*>(in + (size_t)w * 128) + lane);
    acc.x *= dw; acc.y *= dw; acc.z *= dw; acc.w *= dw;

    int i = 0;
    for (; i + 4 <= deg; i += 4) {
        int s0 = __ldg(srcs + beg + i);
        int s1 = __ldg(srcs + beg + i + 1);
        int s2 = __ldg(srcs + beg + i + 2);
        int s3 = __ldg(srcs + beg + i + 3);
        float d0 = __ldg(dinv + s0), d1 = __ldg(dinv + s1);
        float d2 = __ldg(dinv + s2), d3 = __ldg(dinv + s3);
        float4 v0 = __ldg(reinterpret_cast<const float4*>(in + (size_t)s0 * 128) + lane);
        float4 v1 = __ldg(reinterpret_cast<const float4*>(in + (size_t)s1 * 128) + lane);
        float4 v2 = __ldg(reinterpret_cast<const float4*>(in + (size_t)s2 * 128) + lane);
        float4 v3 = __ldg(reinterpret_cast<const float4*>(in + (size_t)s3 * 128) + lane);
        acc.x = fmaf(v0.x, d0, acc.x); acc.y = fmaf(v0.y, d0, acc.y);
        acc.z = fmaf(v0.z, d0, acc.z); acc.w = fmaf(v0.w, d0, acc.w);
        acc.x = fmaf(v1.x, d1, acc.x); acc.y = fmaf(v1.y, d1, acc.y);
        acc.z = fmaf(v1.z, d1, acc.z); acc.w = fmaf(v1.w, d1, acc.w);
        acc.x = fmaf(v2.x, d2, acc.x); acc.y = fmaf(v2.y, d2, acc.y);
        acc.z = fmaf(v2.z, d2, acc.z); acc.w = fmaf(v2.w, d2, acc.w);
        acc.x = fmaf(v3.x, d3, acc.x); acc.y = fmaf(v3.y, d3, acc.y);
        acc.z = fmaf(v3.z, d3, acc.z); acc.w = fmaf(v3.w, d3, acc.w);
    }
    for (; i < deg; i++) {
        int s = __ldg(srcs + beg + i);
        float ds = __ldg(dinv + s);
        float4 v = __ldg(reinterpret_cast<const float4*>(in + (size_t)s * 128) + lane);
        acc.x = fmaf(v.x, ds, acc.x); acc.y = fmaf(v.y, ds, acc.y);
        acc.z = fmaf(v.z, ds, acc.z); acc.w = fmaf(v.w, ds, acc.w);
    }
    acc.x *= dw; acc.y *= dw; acc.z *= dw; acc.w *= dw;
    atomicAdd(reinterpret_cast<float4*>(pool + (size_t)b * 128) + lane, acc);
    if (lane == 0) atomicAdd(cnt + b, 1.0f);
}

// ---------------- mma.sync GEMM: C[128, 128] tile of A[M,K] @ Bt^T ----------
// A as bf16 hi/lo [M][K_TOT]; Bt as bf16 hi/lo [N][K_TOT] (row = output col).
// 3-pass compensated bf16: A_hi*B_hi + A_hi*B_lo + A_lo*B_hi, fp32 reg accum.
// 256 thr = 8 warps, warp tile 64x32 (2x4 warp grid), BK = 64.
// SPLIT_OUT: out = relu(C + bias) as bf16 hi/lo. Else: fp32 out.
#define LDS_B 72          // smem row stride in bf16 (144 bytes)
#define TILE_SM (128 * LDS_B * 2)   // 18432 bytes per 128x64 tile
#define GEMM_SMEM (512 + 4 * TILE_SM)

template<bool SPLIT_OUT>
__global__ __launch_bounds__(256, 2)
void gemm_mma_kernel(const __nv_bfloat16* __restrict__ Ah, const __nv_bfloat16* __restrict__ Al,
                     const __nv_bfloat16* __restrict__ Bh, const __nv_bfloat16* __restrict__ Bl,
                     const float* __restrict__ bias,
                     __nv_bfloat16* __restrict__ Oh, __nv_bfloat16* __restrict__ Ol,
                     float* __restrict__ Of,
                     int M, int K_TOT, int N_STRIDE)
{
    extern __shared__ __align__(16) char smem[];
    float* sbias = reinterpret_cast<float*>(smem);
    __nv_bfloat16* sAh = reinterpret_cast<__nv_bfloat16*>(smem + 512);
    __nv_bfloat16* sAl = reinterpret_cast<__nv_bfloat16*>(smem + 512 + TILE_SM);
    __nv_bfloat16* sBh = reinterpret_cast<__nv_bfloat16*>(smem + 512 + 2 * TILE_SM);
    __nv_bfloat16* sBl = reinterpret_cast<__nv_bfloat16*>(smem + 512 + 3 * TILE_SM);

    const int tid = threadIdx.x;
    const int wid = tid >> 5, lane = tid & 31;
    const int g = lane >> 2, tg = lane & 3;
    const int bm = blockIdx.x * 128;
    const int nybase = blockIdx.y * 128;
    const int wm = (wid & 1) * 64;       // warp M offset
    const int wn = (wid >> 1) * 32;      // warp N offset

    if (SPLIT_OUT && tid < 128) sbias[tid] = bias[nybase + tid];

    float c[4][4][4];
#pragma unroll
    for (int mi = 0; mi < 4; mi++)
#pragma unroll
        for (int nj = 0; nj < 4; nj++)
#pragma unroll
            for (int q = 0; q < 4; q++) c[mi][nj][q] = 0.f;

    for (int kc = 0; kc < K_TOT; kc += 64) {
        // ---- stage 128x64 chunks of Ah/Al/Bh/Bl into smem ----
#pragma unroll
        for (int it = 0; it < 4; it++) {
            int idx = tid + it * 256;           // 0..1023
            int row = idx >> 3, q = idx & 7;    // 8 uint4 per 64-bf16 row
            int m = bm + row; if (m >= M) m = M - 1;
            size_t ga = (size_t)m * K_TOT + kc;
            size_t gb = (size_t)(nybase + row) * K_TOT + kc;
            reinterpret_cast<uint4*>(sAh + row * LDS_B)[q] =
                reinterpret_cast<const uint4*>(Ah + ga)[q];
            reinterpret_cast<uint4*>(sAl + row * LDS_B)[q] =
                reinterpret_cast<const uint4*>(Al + ga)[q];
            reinterpret_cast<uint4*>(sBh + row * LDS_B)[q] =
                reinterpret_cast<const uint4*>(Bh + gb)[q];
            reinterpret_cast<uint4*>(sBl + row * LDS_B)[q] =
                reinterpret_cast<const uint4*>(Bl + gb)[q];
        }
        __syncthreads();

#pragma unroll
        for (int ks = 0; ks < 4; ks++) {
            const int k0 = ks * 16;
            uint32_t fbh[4][2], fbl[4][2];
#pragma unroll
            for (int nj = 0; nj < 4; nj++) {
                const __nv_bfloat16* ph = sBh + (wn + nj * 8 + g) * LDS_B + k0 + tg * 2;
                fbh[nj][0] = *reinterpret_cast<const uint32_t*>(ph);
                fbh[nj][1] = *reinterpret_cast<const uint32_t*>(ph + 8);
                const __nv_bfloat16* pl = sBl + (wn + nj * 8 + g) * LDS_B + k0 + tg * 2;
                fbl[nj][0] = *reinterpret_cast<const uint32_t*>(pl);
                fbl[nj][1] = *reinterpret_cast<const uint32_t*>(pl + 8);
            }
#pragma unroll
            for (int mi = 0; mi < 4; mi++) {
                const __nv_bfloat16* pah = sAh + (wm + mi * 16 + g) * LDS_B + k0 + tg * 2;
                uint32_t ah0 = *reinterpret_cast<const uint32_t*>(pah);
                uint32_t ah1 = *reinterpret_cast<const uint32_t*>(pah + 8 * LDS_B);
                uint32_t ah2 = *reinterpret_cast<const uint32_t*>(pah + 8);
                uint32_t ah3 = *reinterpret_cast<const uint32_t*>(pah + 8 * LDS_B + 8);
                const __nv_bfloat16* pal = sAl + (wm + mi * 16 + g) * LDS_B + k0 + tg * 2;
                uint32_t al0 = *reinterpret_cast<const uint32_t*>(pal);
                uint32_t al1 = *reinterpret_cast<const uint32_t*>(pal + 8 * LDS_B);
                uint32_t al2 = *reinterpret_cast<const uint32_t*>(pal + 8);
                uint32_t al3 = *reinterpret_cast<const uint32_t*>(pal + 8 * LDS_B + 8);
#pragma unroll
                for (int nj = 0; nj < 4; nj++) {
                    MMA_BF16(c[mi][nj], ah0, ah1, ah2, ah3, fbh[nj][0], fbh[nj][1]);
                    MMA_BF16(c[mi][nj], ah0, ah1, ah2, ah3, fbl[nj][0], fbl[nj][1]);
                    MMA_BF16(c[mi][nj], al0, al1, al2, al3, fbh[nj][0], fbh[nj][1]);
                }
            }
        }
        __syncthreads();
    }

    // ---- epilogue ----
#pragma unroll
    for (int mi = 0; mi < 4; mi++) {
        const int r0 = bm + wm + mi * 16 + g;
        const int r1 = r0 + 8;
#pragma unroll
        for (int nj = 0; nj < 4; nj++) {
            const int col = wn + nj * 8 + tg * 2;   // local col (even)
            const int gc = nybase + col;
            float v0 = c[mi][nj][0], v1 = c[mi][nj][1];
            float v2 = c[mi][nj][2], v3 = c[mi][nj][3];
            if (SPLIT_OUT) {
                const float b0 = sbias[col], b1 = sbias[col + 1];
                v0 = fmaxf(v0 + b0, 0.f); v1 = fmaxf(v1 + b1, 0.f);
                v2 = fmaxf(v2 + b0, 0.f); v3 = fmaxf(v3 + b1, 0.f);
                __nv_bfloat16 h0 = __float2bfloat16(v0), h1 = __float2bfloat16(v1);
                __nv_bfloat16 h2 = __float2bfloat16(v2), h3 = __float2bfloat16(v3);
                float l0 = v0 - __bfloat162float(h0), l1 = v1 - __bfloat162float(h1);
                float l2 = v2 - __bfloat162float(h2), l3 = v3 - __bfloat162float(h3);
                if (r0 < M) {
                    *reinterpret_cast<uint32_t*>(Oh + (size_t)r0 * N_STRIDE + gc) = pack_bf2(h0, h1);
                    *reinterpret_cast<uint32_t*>(Ol + (size_t)r0 * N_STRIDE + gc) =
                        pack_bf2(__float2bfloat16(l0), __float2bfloat16(l1));
                }
                if (r1 < M) {
                    *reinterpret_cast<uint32_t*>(Oh + (size_t)r1 * N_STRIDE + gc) = pack_bf2(h2, h3);
                    *reinterpret_cast<uint32_t*>(Ol + (size_t)r1 * N_STRIDE + gc) =
                        pack_bf2(__float2bfloat16(l2), __float2bfloat16(l3));
                }
            } else {
                if (r0 < M)
                    *reinterpret_cast<float2*>(Of + (size_t)r0 * N_STRIDE + gc) = make_float2(v0, v1);
                if (r1 < M)
                    *reinterpret_cast<float2*>(Of + (size_t)r1 * N_STRIDE + gc) = make_float2(v2, v3);
            }
        }
    }
}

// ---------------- head: emb, group logits, argmax, family logits -----------
__global__ __launch_bounds__(128)
void head_kernel(const float* __restrict__ b2, const float* __restrict__ Wg,
                 const float* __restrict__ bg, const float* __restrict__ Wf,
                 const float* __restrict__ bf,
                 const float* __restrict__ pool, const float* __restrict__ cnt,
                 float* __restrict__ out_emb, float* __restrict__ out_gl,
                 float* __restrict__ out_fam)
{
    const int b = blockIdx.x;
    const int t = threadIdx.x;
    __shared__ float s_emb[EMB_D];
    __shared__ float s_lg[G_GRP];
    __shared__ int s_grp;

    float c = cnt[b];
    float e = 0.f;
    if (c > 0.f) e = pool[(size_t)b * EMB_D + t] / c + b2[t];
    out_emb[(size_t)b * EMB_D + t] = e;
    s_emb[t] = e;
    __syncthreads();

    if (t < G_GRP) {
        float lg = bg[t];
#pragma unroll 8
        for (int k = 0; k < EMB_D; k++)
            lg = fmaf(s_emb[k], Wg[k * G_GRP + t], lg);
        out_gl[(size_t)b * G_GRP + t] = lg;
        s_lg[t] = lg;
    }
    __syncthreads();

    if (t == 0) {
        int gm = 0; float m = s_lg[0];
#pragma unroll
        for (int j = 1; j < G_GRP; j++)
            if (s_lg[j] > m) { m = s_lg[j]; gm = j; }
        s_grp = gm;
    }
    __syncthreads();

    const int g = s_grp;
    if (t < FAM_C) {
        float v = bf[g * FAM_C + t];
        const float* wf = Wf + (size_t)g * EMB_D * FAM_C + t;
#pragma unroll 8
        for (int k = 0; k < EMB_D; k++)
            v = fmaf(s_emb[k], wf[(size_t)k * FAM_C], v);
        out_fam[((size_t)g * B_GR + b) * FAM_C + t] = v;
    }
}

// ---------------- launch ----------------
extern "C" void kernel_launch(void* const* d_in, const int* in_sizes, int n_in,
                              void* d_out, int out_size)
{
    const float* x    = (const float*)d_in[0];
    const float* W1   = (const float*)d_in[1];
    const float* b1   = (const float*)d_in[2];
    const float* W2   = (const float*)d_in[3];
    const float* b2   = (const float*)d_in[4];
    const float* Wg   = (const float*)d_in[5];
    const float* bg   = (const float*)d_in[6];
    const float* Wf   = (const float*)d_in[7];
    const float* bf   = (const float*)d_in[8];
    const int*   edge = (const int*)d_in[9];
    const int*   batch= (const int*)d_in[10];

    const int E = in_sizes[9] / 2;
    const int n = in_sizes[10];
    const int nb = (n + 1023) / 1024;

    int *counts, *rowptr, *cursor, *srcs, *bsums;
    float *dinv, *hw2, *poolcnt;
    __nv_bfloat16 *ah, *al, *h1h, *h1l, *w1h, *w1l, *w2h, *w2l;
    cudaGetSymbolAddress((void**)&counts, g_counts);
    cudaGetSymbolAddress((void**)&rowptr, g_rowptr);
    cudaGetSymbolAddress((void**)&cursor, g_cursor);
    cudaGetSymbolAddress((void**)&srcs,   g_srcs);
    cudaGetSymbolAddress((void**)&bsums,  g_bsums);
    cudaGetSymbolAddress((void**)&dinv,   g_dinv);
    cudaGetSymbolAddress((void**)&ah,     g_a_h);
    cudaGetSymbolAddress((void**)&al,     g_a_l);
    cudaGetSymbolAddress((void**)&h1h,    g_h1h);
    cudaGetSymbolAddress((void**)&h1l,    g_h1l);
    cudaGetSymbolAddress((void**)&hw2,    g_hw2);
    cudaGetSymbolAddress((void**)&w1h,    g_w1h);
    cudaGetSymbolAddress((void**)&w1l,    g_w1l);
    cudaGetSymbolAddress((void**)&w2h,    g_w2h);
    cudaGetSymbolAddress((void**)&w2l,    g_w2l);
    cudaGetSymbolAddress((void**)&poolcnt,g_pool);
    float* pool = poolcnt;
    float* cnt  = poolcnt + (size_t)B_GR * EMB_D;

    float* out = (float*)d_out;
    float* out_emb = out;
    float* out_gl  = out + (size_t)B_GR * EMB_D;
    float* out_fam = out_gl + (size_t)B_GR * G_GRP;

    const int* src = edge;
    const int* dst = edge + E;

    cudaFuncSetAttribute(gemm_mma_kernel<true>,
                         cudaFuncAttributeMaxDynamicSharedMemorySize, GEMM_SMEM);
    cudaFuncSetAttribute(gemm_mma_kernel<false>,
                         cudaFuncAttributeMaxDynamicSharedMemorySize, GEMM_SMEM);

    // ---- CSR build ----
    zero_int_kernel<<<(n + 255) / 256, 256>>>(counts, n);
    hist_kernel<<<(E / 4 + 255) / 256, 256>>>(dst, counts, E);
    scan_block_kernel<<<nb, 1024>>>(counts, rowptr, bsums, dinv, n);
    scan_sums_kernel<<<1, 1024>>>(bsums, nb);
    scan_add_kernel<<<nb, 1024>>>(rowptr, cursor, bsums, n);
    place_kernel<<<(E / 4 + 255) / 256, 256>>>(src, dst, cursor, srcs, E);

    // ---- weight transpose + split (tiny) ----
    wsplit_kernel<<<(F_IN * H_DIM + 255) / 256, 256>>>(W1, w1h, w1l, F_IN, H_DIM);
    wsplit_kernel<<<(H_DIM * EMB_D + 255) / 256, 256>>>(W2, w2h, w2l, H_DIM, EMB_D);

    // ---- layer 1: gather (fp32 acc -> bf16 hi/lo), then HMMA GEMM ----
    gather_split_kernel<<<(n + 7) / 8, 256>>>(x, ah, al, rowptr, counts, srcs, dinv, n);
    {
        dim3 grid((n + 127) / 128, 2);   // N = 256
        gemm_mma_kernel<true><<<grid, 256, GEMM_SMEM>>>(
            ah, al, w1h, w1l, b1, h1h, h1l, nullptr, n, F_IN, H_DIM);
    }

    // ---- layer 2: HMMA GEMM (fp32 out), then fused gather+pool ----
    {
        dim3 grid((n + 127) / 128, 1);   // N = 128, K = 256
        gemm_mma_kernel<false><<<grid, 256, GEMM_SMEM>>>(
            h1h, h1l, w2h, w2l, nullptr, nullptr, nullptr, hw2, n, H_DIM, EMB_D);
    }
    {
        int n4 = (B_GR * EMB_D + B_GR) / 4;
        fill0f4_kernel<<<(n4 + 255) / 256, 256>>>((float4*)poolcnt, n4);
    }
    gather_pool_kernel<<<(n + 7) / 8, 256>>>(hw2, rowptr, counts, srcs, dinv,
                                             batch, pool, cnt, n);

    // ---- heads ----
    {
        int n4 = (G_GRP * B_GR * FAM_C) / 4;
        fill0f4_kernel<<<(n4 + 255) / 256, 256>>>((float4*)out_fam, n4);
    }
    head_kernel<<<B_GR, 128>>>(b2, Wg, bg, Wf, bf, pool, cnt,
                               out_emb, out_gl, out_fam);
}

// round 14
// speedup vs baseline: 1.0209x; 1.0169x over previous
#include <cuda_runtime.h>
#include <cuda_bf16.h>
#include <cstdint>
#include <cstddef>

// Problem constants
#define N_NODES 100000
#define E_MAX   1600000
#define F_IN    128
#define H_DIM   256
#define EMB_D   128
#define B_GR    1024
#define G_GRP   8
#define FAM_C   100

// ---------------- static device scratch (no allocs allowed) ----------------
__device__ __align__(16) int   g_counts[N_NODES];
__device__ __align__(16) int   g_rowptr[N_NODES];
__device__ __align__(16) int   g_cursor[N_NODES];
__device__ __align__(16) int   g_srcs[E_MAX];
__device__ __align__(16) int   g_bsums[1024];
__device__ __align__(16) float g_dinv[N_NODES];
__device__ __align__(16) __nv_bfloat16 g_a_h[(size_t)N_NODES * F_IN];   // agg1 hi
__device__ __align__(16) __nv_bfloat16 g_a_l[(size_t)N_NODES * F_IN];   // agg1 lo
__device__ __align__(16) __nv_bfloat16 g_h1h[(size_t)N_NODES * H_DIM];  // h1 hi
__device__ __align__(16) __nv_bfloat16 g_h1l[(size_t)N_NODES * H_DIM];  // h1 lo
__device__ __align__(16) float g_hw2[(size_t)N_NODES * EMB_D];          // h1 @ W2 (fp32)
__device__ __align__(16) __nv_bfloat16 g_w1h[H_DIM * F_IN];  // W1^T hi [N=256][K=128]
__device__ __align__(16) __nv_bfloat16 g_w1l[H_DIM * F_IN];
__device__ __align__(16) __nv_bfloat16 g_w2h[EMB_D * H_DIM]; // W2^T hi [N=128][K=256]
__device__ __align__(16) __nv_bfloat16 g_w2l[EMB_D * H_DIM];
__device__ __align__(16) float g_pool[(size_t)B_GR * EMB_D + B_GR];     // pool + cnt

static __device__ __forceinline__ uint32_t pack_bf2(__nv_bfloat16 a, __nv_bfloat16 b) {
    return (uint32_t)__bfloat16_as_ushort(a) | ((uint32_t)__bfloat16_as_ushort(b) << 16);
}

// m16n8k16 bf16 MMA, fp32 accumulate (portable: sm_80+, assembles for sm_103)
#define MMA_BF16(C, A0, A1, A2, A3, B0, B1) \
    asm volatile("mma.sync.aligned.m16n8k16.row.col.f32.bf16.bf16.f32 " \
                 "{%0,%1,%2,%3}, {%4,%5,%6,%7}, {%8,%9}, {%0,%1,%2,%3};" \
                 : "+f"((C)[0]), "+f"((C)[1]), "+f"((C)[2]), "+f"((C)[3]) \
                 : "r"(A0), "r"(A1), "r"(A2), "r"(A3), "r"(B0), "r"(B1))

// ---------------- fused prologue: zero counts + zero pool + wsplit W1/W2 ---
// Segments by blockIdx.x: [0,nb0) counts, [nb0,nb0+nb1) poolcnt,
// [.., +128) wsplit W1 (K=128,N=256), [.., +128) wsplit W2 (K=256,N=128).
__global__ __launch_bounds__(256)
void setup_kernel(int* __restrict__ counts, float4* __restrict__ poolcnt,
                  const float* __restrict__ W1,
                  __nv_bfloat16* __restrict__ w1h, __nv_bfloat16* __restrict__ w1l,
                  const float* __restrict__ W2,
                  __nv_bfloat16* __restrict__ w2h, __nv_bfloat16* __restrict__ w2l,
                  int n, int nb0, int nb1)
{
    const int b = blockIdx.x;
    const int t = threadIdx.x;
    if (b < nb0) {
        int i = b * 256 + t;
        if (i < n) counts[i] = 0;
    } else if (b < nb0 + nb1) {
        int i = (b - nb0) * 256 + t;
        if (i < (B_GR * EMB_D + B_GR) / 4)
            poolcnt[i] = make_float4(0.f, 0.f, 0.f, 0.f);
    } else if (b < nb0 + nb1 + 128) {
        int i = (b - nb0 - nb1) * 256 + t;          // i < 32768 = F_IN*H_DIM
        int k = i / H_DIM, nn = i - k * H_DIM;
        float v = W1[i];
        __nv_bfloat16 h = __float2bfloat16(v);
        float l = v - __bfloat162float(h);
        w1h[(size_t)nn * F_IN + k] = h;
        w1l[(size_t)nn * F_IN + k] = __float2bfloat16(l);
    } else {
        int i = (b - nb0 - nb1 - 128) * 256 + t;    // i < 32768 = H_DIM*EMB_D
        int k = i / EMB_D, nn = i - k * EMB_D;
        float v = W2[i];
        __nv_bfloat16 h = __float2bfloat16(v);
        float l = v - __bfloat162float(h);
        w2h[(size_t)nn * H_DIM + k] = h;
        w2l[(size_t)nn * H_DIM + k] = __float2bfloat16(l);
    }
}

// 4-wide vectorized degree histogram
__global__ void hist_kernel(const int* __restrict__ dst, int* __restrict__ counts, int e) {
    int i = blockIdx.x * blockDim.x + threadIdx.x;
    int i4 = i * 4;
    if (i4 + 3 < e) {
        int4 d = __ldg(reinterpret_cast<const int4*>(dst) + i);
        atomicAdd(counts + d.x, 1);
        atomicAdd(counts + d.y, 1);
        atomicAdd(counts + d.z, 1);
        atomicAdd(counts + d.w, 1);
    } else {
        for (int j = i4; j < e; j++) atomicAdd(counts + __ldg(dst + j), 1);
    }
}

// ---------------- 3-step exclusive scan of counts -> rowptr (+ dinv) -------
__global__ __launch_bounds__(1024)
void scan_block_kernel(const int* __restrict__ counts, int* __restrict__ rp,
                       int* __restrict__ bsums, float* __restrict__ dinv, int n)
{
    __shared__ int sh[1024];
    const int tid = threadIdx.x;
    const int i = blockIdx.x * 1024 + tid;
    int v = (i < n) ? counts[i] : 0;
    if (i < n) dinv[i] = rsqrtf((float)(v + 1));   // +1 self loop
    sh[tid] = v;
    __syncthreads();
#pragma unroll
    for (int off = 1; off < 1024; off <<= 1) {
        int t = 0;
        if (tid >= off) t = sh[tid - off];
        __syncthreads();
        if (tid >= off) sh[tid] += t;
        __syncthreads();
    }
    if (i < n) rp[i] = sh[tid] - v;
    if (tid == 1023) bsums[blockIdx.x] = sh[1023];
}

// parallel exclusive scan of block sums (nb <= 1024)
__global__ __launch_bounds__(1024)
void scan_sums_kernel(int* __restrict__ bsums, int nb) {
    __shared__ int sh[1024];
    const int tid = threadIdx.x;
    int v = (tid < nb) ? bsums[tid] : 0;
    sh[tid] = v;
    __syncthreads();
#pragma unroll
    for (int off = 1; off < 1024; off <<= 1) {
        int t = 0;
        if (tid >= off) t = sh[tid - off];
        __syncthreads();
        if (tid >= off) sh[tid] += t;
        __syncthreads();
    }
    if (tid < nb) bsums[tid] = sh[tid] - v;   // exclusive
}

__global__ __launch_bounds__(1024)
void scan_add_kernel(int* __restrict__ rp, int* __restrict__ cursor,
                     const int* __restrict__ bsums, int n)
{
    int i = blockIdx.x * 1024 + threadIdx.x;
    if (i < n) {
        int v = rp[i] + bsums[blockIdx.x];
        rp[i] = v;
        cursor[i] = v;
    }
}

// 4-wide vectorized CSR placement
__global__ void place_kernel(const int* __restrict__ src, const int* __restrict__ dst,
                             int* __restrict__ cursor, int* __restrict__ srcs, int e)
{
    int i = blockIdx.x * blockDim.x + threadIdx.x;
    int i4 = i * 4;
    if (i4 + 3 < e) {
        int4 d = __ldg(reinterpret_cast<const int4*>(dst) + i);
        int4 s = __ldg(reinterpret_cast<const int4*>(src) + i);
        srcs[atomicAdd(cursor + d.x, 1)] = s.x;
        srcs[atomicAdd(cursor + d.y, 1)] = s.y;
        srcs[atomicAdd(cursor + d.z, 1)] = s.z;
        srcs[atomicAdd(cursor + d.w, 1)] = s.w;
    } else {
        for (int j = i4; j < e; j++) {
            int d = __ldg(dst + j);
            srcs[atomicAdd(cursor + d, 1)] = __ldg(src + j);
        }
    }
}

// ---------------- CSR gather (layer 1) -> bf16 hi/lo split output ----------
__global__ __launch_bounds__(256)
void gather_split_kernel(const float* __restrict__ in,
                         __nv_bfloat16* __restrict__ oh, __nv_bfloat16* __restrict__ ol,
                         const int* __restrict__ rowptr, const int* __restrict__ counts,
                         const int* __restrict__ srcs, const float* __restrict__ dinv,
                         int n)
{
    const int w = (blockIdx.x * 256 + threadIdx.x) >> 5;
    const int lane = threadIdx.x & 31;
    if (w >= n) return;

    const int beg = __ldg(rowptr + w);
    const int deg = __ldg(counts + w);
    const float dw = __ldg(dinv + w);

    float4 acc = __ldg(reinterpret_cast<const float4*>(in + (size_t)w * 128) + lane);
    acc.x *= dw; acc.y *= dw; acc.z *= dw; acc.w *= dw;

    int i = 0;
    for (; i + 4 <= deg; i += 4) {
        int s0 = __ldg(srcs + beg + i);
        int s1 = __ldg(srcs + beg + i + 1);
        int s2 = __ldg(srcs + beg + i + 2);
        int s3 = __ldg(srcs + beg + i + 3);
        float d0 = __ldg(dinv + s0), d1 = __ldg(dinv + s1);
        float d2 = __ldg(dinv + s2), d3 = __ldg(dinv + s3);
        float4 v0 = __ldg(reinterpret_cast<const float4*>(in + (size_t)s0 * 128) + lane);
        float4 v1 = __ldg(reinterpret_cast<const float4*>(in + (size_t)s1 * 128) + lane);
        float4 v2 = __ldg(reinterpret_cast<const float4*>(in + (size_t)s2 * 128) + lane);
        float4 v3 = __ldg(reinterpret_cast<const float4*>(in + (size_t)s3 * 128) + lane);
        acc.x = fmaf(v0.x, d0, acc.x); acc.y = fmaf(v0.y, d0, acc.y);
        acc.z = fmaf(v0.z, d0, acc.z); acc.w = fmaf(v0.w, d0, acc.w);
        acc.x = fmaf(v1.x, d1, acc.x); acc.y = fmaf(v1.y, d1, acc.y);
        acc.z = fmaf(v1.z, d1, acc.z); acc.w = fmaf(v1.w, d1, acc.w);
        acc.x = fmaf(v2.x, d2, acc.x); acc.y = fmaf(v2.y, d2, acc.y);
        acc.z = fmaf(v2.z, d2, acc.z); acc.w = fmaf(v2.w, d2, acc.w);
        acc.x = fmaf(v3.x, d3, acc.x); acc.y = fmaf(v3.y, d3, acc.y);
        acc.z = fmaf(v3.z, d3, acc.z); acc.w = fmaf(v3.w, d3, acc.w);
    }
    for (; i < deg; i++) {
        int s = __ldg(srcs + beg + i);
        float ds = __ldg(dinv + s);
        float4 v = __ldg(reinterpret_cast<const float4*>(in + (size_t)s * 128) + lane);
        acc.x = fmaf(v.x, ds, acc.x); acc.y = fmaf(v.y, ds, acc.y);
        acc.z = fmaf(v.z, ds, acc.z); acc.w = fmaf(v.w, ds, acc.w);
    }
    acc.x *= dw; acc.y *= dw; acc.z *= dw; acc.w *= dw;

    __nv_bfloat16 hx = __float2bfloat16(acc.x), hy = __float2bfloat16(acc.y);
    __nv_bfloat16 hz = __float2bfloat16(acc.z), hw2 = __float2bfloat16(acc.w);
    float lx = acc.x - __bfloat162float(hx), ly = acc.y - __bfloat162float(hy);
    float lz = acc.z - __bfloat162float(hz), lw = acc.w - __bfloat162float(hw2);
    uint2 hv, lv;
    hv.x = pack_bf2(hx, hy); hv.y = pack_bf2(hz, hw2);
    lv.x = pack_bf2(__float2bfloat16(lx), __float2bfloat16(ly));
    lv.y = pack_bf2(__float2bfloat16(lz), __float2bfloat16(lw));
    reinterpret_cast<uint2*>(oh + (size_t)w * 128)[lane] = hv;
    reinterpret_cast<uint2*>(ol + (size_t)w * 128)[lane] = lv;
}

// ---------------- fused layer-2 gather + mean-pool accumulation ----------------
__global__ __launch_bounds__(256)
void gather_pool_kernel(const float* __restrict__ in,
                        const int* __restrict__ rowptr, const int* __restrict__ counts,
                        const int* __restrict__ srcs, const float* __restrict__ dinv,
                        const int* __restrict__ batch,
                        float* __restrict__ pool, float* __restrict__ cnt, int n)
{
    const int w = (blockIdx.x * 256 + threadIdx.x) >> 5;
    const int lane = threadIdx.x & 31;
    if (w >= n) return;

    const int beg = __ldg(rowptr + w);
    const int deg = __ldg(counts + w);
    const float dw = __ldg(dinv + w);
    const int b = __ldg(batch + w);

    float4 acc = __ldg(reinterpret_cast<const float4*>(in + (size_t)w * 128) + lane);
    acc.x *= dw; acc.y *= dw; acc.z *= dw; acc.w *= dw;

    int i = 0;
    for (; i + 4 <= deg; i += 4) {
        int s0 = __ldg(srcs + beg + i);
        int s1 = __ldg(srcs + beg + i + 1);
        int s2 = __ldg(srcs + beg + i + 2);
        int s3 = __ldg(srcs + beg + i + 3);
        float d0 = __ldg(dinv + s0), d1 = __ldg(dinv + s1);
        float d2 = __ldg(dinv + s2), d3 = __ldg(dinv + s3);
        float4 v0 = __ldg(reinterpret_cast<const float4*>(in + (size_t)s0 * 128) + lane);
        float4 v1 = __ldg(reinterpret_cast<const float4*>(in + (size_t)s1 * 128) + lane);
        float4 v2 = __ldg(reinterpret_cast<const float4*>(in + (size_t)s2 * 128) + lane);
        float4 v3 = __ldg(reinterpret_cast<const float4*>(in + (size_t)s3 * 128) + lane);
        acc.x = fmaf(v0.x, d0, acc.x); acc.y = fmaf(v0.y, d0, acc.y);
        acc.z = fmaf(v0.z, d0, acc.z); acc.w = fmaf(v0.w, d0, acc.w);
        acc.x = fmaf(v1.x, d1, acc.x); acc.y = fmaf(v1.y, d1, acc.y);
        acc.z = fmaf(v1.z, d1, acc.z); acc.w = fmaf(v1.w, d1, acc.w);
        acc.x = fmaf(v2.x, d2, acc.x); acc.y = fmaf(v2.y, d2, acc.y);
        acc.z = fmaf(v2.z, d2, acc.z); acc.w = fmaf(v2.w, d2, acc.w);
        acc.x = fmaf(v3.x, d3, acc.x); acc.y = fmaf(v3.y, d3, acc.y);
        acc.z = fmaf(v3.z, d3, acc.z); acc.w = fmaf(v3.w, d3, acc.w);
    }
    for (; i < deg; i++) {
        int s = __ldg(srcs + beg + i);
        float ds = __ldg(dinv + s);
        float4 v = __ldg(reinterpret_cast<const float4*>(in + (size_t)s * 128) + lane);
        acc.x = fmaf(v.x, ds, acc.x); acc.y = fmaf(v.y, ds, acc.y);
        acc.z = fmaf(v.z, ds, acc.z); acc.w = fmaf(v.w, ds, acc.w);
    }
    acc.x *= dw; acc.y *= dw; acc.z *= dw; acc.w *= dw;
    atomicAdd(reinterpret_cast<float4*>(pool + (size_t)b * 128) + lane, acc);
    if (lane == 0) atomicAdd(cnt + b, 1.0f);
}

// ---------------- mma.sync GEMM: C[128, 128] tile of A[M,K] @ Bt^T ----------
// A as bf16 hi/lo [M][K_TOT]; Bt as bf16 hi/lo [N][K_TOT] (row = output col).
// 3-pass compensated bf16: A_hi*B_hi + A_hi*B_lo + A_lo*B_hi, fp32 reg accum.
// 256 thr = 8 warps, warp tile 64x32 (2x4 warp grid), BK = 64.
// SPLIT_OUT: out = relu(C + bias) as bf16 hi/lo. Else: fp32 out.
#define LDS_B 72          // smem row stride in bf16 (144 bytes)
#define TILE_SM (128 * LDS_B * 2)   // 18432 bytes per 128x64 tile
#define GEMM_SMEM (512 + 4 * TILE_SM)

template<bool SPLIT_OUT>
__global__ __launch_bounds__(256, 2)
void gemm_mma_kernel(const __nv_bfloat16* __restrict__ Ah, const __nv_bfloat16* __restrict__ Al,
                     const __nv_bfloat16* __restrict__ Bh, const __nv_bfloat16* __restrict__ Bl,
                     const float* __restrict__ bias,
                     __nv_bfloat16* __restrict__ Oh, __nv_bfloat16* __restrict__ Ol,
                     float* __restrict__ Of,
                     int M, int K_TOT, int N_STRIDE)
{
    extern __shared__ __align__(16) char smem[];
    float* sbias = reinterpret_cast<float*>(smem);
    __nv_bfloat16* sAh = reinterpret_cast<__nv_bfloat16*>(smem + 512);
    __nv_bfloat16* sAl = reinterpret_cast<__nv_bfloat16*>(smem + 512 + TILE_SM);
    __nv_bfloat16* sBh = reinterpret_cast<__nv_bfloat16*>(smem + 512 + 2 * TILE_SM);
    __nv_bfloat16* sBl = reinterpret_cast<__nv_bfloat16*>(smem + 512 + 3 * TILE_SM);

    const int tid = threadIdx.x;
    const int wid = tid >> 5, lane = tid & 31;
    const int g = lane >> 2, tg = lane & 3;
    const int bm = blockIdx.x * 128;
    const int nybase = blockIdx.y * 128;
    const int wm = (wid & 1) * 64;       // warp M offset
    const int wn = (wid >> 1) * 32;      // warp N offset

    if (SPLIT_OUT && tid < 128) sbias[tid] = bias[nybase + tid];

    float c[4][4][4];
#pragma unroll
    for (int mi = 0; mi < 4; mi++)
#pragma unroll
        for (int nj = 0; nj < 4; nj++)
#pragma unroll
            for (int q = 0; q < 4; q++) c[mi][nj][q] = 0.f;

    for (int kc = 0; kc < K_TOT; kc += 64) {
        // ---- stage 128x64 chunks of Ah/Al/Bh/Bl into smem ----
#pragma unroll
        for (int it = 0; it < 4; it++) {
            int idx = tid + it * 256;           // 0..1023
            int row = idx >> 3, q = idx & 7;    // 8 uint4 per 64-bf16 row
            int m = bm + row; if (m >= M) m = M - 1;
            size_t ga = (size_t)m * K_TOT + kc;
            size_t gb = (size_t)(nybase + row) * K_TOT + kc;
            reinterpret_cast<uint4*>(sAh + row * LDS_B)[q] =
                reinterpret_cast<const uint4*>(Ah + ga)[q];
            reinterpret_cast<uint4*>(sAl + row * LDS_B)[q] =
                reinterpret_cast<const uint4*>(Al + ga)[q];
            reinterpret_cast<uint4*>(sBh + row * LDS_B)[q] =
                reinterpret_cast<const uint4*>(Bh + gb)[q];
            reinterpret_cast<uint4*>(sBl + row * LDS_B)[q] =
                reinterpret_cast<const uint4*>(Bl + gb)[q];
        }
        __syncthreads();

#pragma unroll
        for (int ks = 0; ks < 4; ks++) {
            const int k0 = ks * 16;
            uint32_t fbh[4][2], fbl[4][2];
#pragma unroll
            for (int nj = 0; nj < 4; nj++) {
                const __nv_bfloat16* ph = sBh + (wn + nj * 8 + g) * LDS_B + k0 + tg * 2;
                fbh[nj][0] = *reinterpret_cast<const uint32_t*>(ph);
                fbh[nj][1] = *reinterpret_cast<const uint32_t*>(ph + 8);
                const __nv_bfloat16* pl = sBl + (wn + nj * 8 + g) * LDS_B + k0 + tg * 2;
                fbl[nj][0] = *reinterpret_cast<const uint32_t*>(pl);
                fbl[nj][1] = *reinterpret_cast<const uint32_t*>(pl + 8);
            }
#pragma unroll
            for (int mi = 0; mi < 4; mi++) {
                const __nv_bfloat16* pah = sAh + (wm + mi * 16 + g) * LDS_B + k0 + tg * 2;
                uint32_t ah0 = *reinterpret_cast<const uint32_t*>(pah);
                uint32_t ah1 = *reinterpret_cast<const uint32_t*>(pah + 8 * LDS_B);
                uint32_t ah2 = *reinterpret_cast<const uint32_t*>(pah + 8);
                uint32_t ah3 = *reinterpret_cast<const uint32_t*>(pah + 8 * LDS_B + 8);
                const __nv_bfloat16* pal = sAl + (wm + mi * 16 + g) * LDS_B + k0 + tg * 2;
                uint32_t al0 = *reinterpret_cast<const uint32_t*>(pal);
                uint32_t al1 = *reinterpret_cast<const uint32_t*>(pal + 8 * LDS_B);
                uint32_t al2 = *reinterpret_cast<const uint32_t*>(pal + 8);
                uint32_t al3 = *reinterpret_cast<const uint32_t*>(pal + 8 * LDS_B + 8);
#pragma unroll
                for (int nj = 0; nj < 4; nj++) {
                    MMA_BF16(c[mi][nj], ah0, ah1, ah2, ah3, fbh[nj][0], fbh[nj][1]);
                    MMA_BF16(c[mi][nj], ah0, ah1, ah2, ah3, fbl[nj][0], fbl[nj][1]);
                    MMA_BF16(c[mi][nj], al0, al1, al2, al3, fbh[nj][0], fbh[nj][1]);
                }
            }
        }
        __syncthreads();
    }

    // ---- epilogue ----
#pragma unroll
    for (int mi = 0; mi < 4; mi++) {
        const int r0 = bm + wm + mi * 16 + g;
        const int r1 = r0 + 8;
#pragma unroll
        for (int nj = 0; nj < 4; nj++) {
            const int col = wn + nj * 8 + tg * 2;   // local col (even)
            const int gc = nybase + col;
            float v0 = c[mi][nj][0], v1 = c[mi][nj][1];
            float v2 = c[mi][nj][2], v3 = c[mi][nj][3];
            if (SPLIT_OUT) {
                const float b0 = sbias[col], b1 = sbias[col + 1];
                v0 = fmaxf(v0 + b0, 0.f); v1 = fmaxf(v1 + b1, 0.f);
                v2 = fmaxf(v2 + b0, 0.f); v3 = fmaxf(v3 + b1, 0.f);
                __nv_bfloat16 h0 = __float2bfloat16(v0), h1 = __float2bfloat16(v1);
                __nv_bfloat16 h2 = __float2bfloat16(v2), h3 = __float2bfloat16(v3);
                float l0 = v0 - __bfloat162float(h0), l1 = v1 - __bfloat162float(h1);
                float l2 = v2 - __bfloat162float(h2), l3 = v3 - __bfloat162float(h3);
                if (r0 < M) {
                    *reinterpret_cast<uint32_t*>(Oh + (size_t)r0 * N_STRIDE + gc) = pack_bf2(h0, h1);
                    *reinterpret_cast<uint32_t*>(Ol + (size_t)r0 * N_STRIDE + gc) =
                        pack_bf2(__float2bfloat16(l0), __float2bfloat16(l1));
                }
                if (r1 < M) {
                    *reinterpret_cast<uint32_t*>(Oh + (size_t)r1 * N_STRIDE + gc) = pack_bf2(h2, h3);
                    *reinterpret_cast<uint32_t*>(Ol + (size_t)r1 * N_STRIDE + gc) =
                        pack_bf2(__float2bfloat16(l2), __float2bfloat16(l3));
                }
            } else {
                if (r0 < M)
                    *reinterpret_cast<float2*>(Of + (size_t)r0 * N_STRIDE + gc) = make_float2(v0, v1);
                if (r1 < M)
                    *reinterpret_cast<float2*>(Of + (size_t)r1 * N_STRIDE + gc) = make_float2(v2, v3);
            }
        }
    }
}

// ---------------- head: emb, group logits, argmax, family logits -----------
// Also writes zeros into non-member fam rows (replaces the separate fill pass).
__global__ __launch_bounds__(128)
void head_kernel(const float* __restrict__ b2, const float* __restrict__ Wg,
                 const float* __restrict__ bg, const float* __restrict__ Wf,
                 const float* __restrict__ bf,
                 const float* __restrict__ pool, const float* __restrict__ cnt,
                 float* __restrict__ out_emb, float* __restrict__ out_gl,
                 float* __restrict__ out_fam)
{
    const int b = blockIdx.x;
    const int t = threadIdx.x;
    __shared__ float s_emb[EMB_D];
    __shared__ float s_lg[G_GRP];
    __shared__ int s_grp;

    float c = cnt[b];
    float e = 0.f;
    if (c > 0.f) e = pool[(size_t)b * EMB_D + t] / c + b2[t];
    out_emb[(size_t)b * EMB_D + t] = e;
    s_emb[t] = e;
    __syncthreads();

    if (t < G_GRP) {
        float lg = bg[t];
#pragma unroll 8
        for (int k = 0; k < EMB_D; k++)
            lg = fmaf(s_emb[k], Wg[k * G_GRP + t], lg);
        out_gl[(size_t)b * G_GRP + t] = lg;
        s_lg[t] = lg;
    }
    __syncthreads();

    if (t == 0) {
        int gm = 0; float m = s_lg[0];
#pragma unroll
        for (int j = 1; j < G_GRP; j++)
            if (s_lg[j] > m) { m = s_lg[j]; gm = j; }
        s_grp = gm;
    }
    __syncthreads();

    const int g = s_grp;
    if (t < FAM_C) {
        float v = bf[g * FAM_C + t];
        const float* wf = Wf + (size_t)g * EMB_D * FAM_C + t;
#pragma unroll 8
        for (int k = 0; k < EMB_D; k++)
            v = fmaf(s_emb[k], wf[(size_t)k * FAM_C], v);
#pragma unroll
        for (int gg = 0; gg < G_GRP; gg++)
            out_fam[((size_t)gg * B_GR + b) * FAM_C + t] = (gg == g) ? v : 0.f;
    }
}

// ---------------- launch ----------------
extern "C" void kernel_launch(void* const* d_in, const int* in_sizes, int n_in,
                              void* d_out, int out_size)
{
    const float* x    = (const float*)d_in[0];
    const float* W1   = (const float*)d_in[1];
    const float* b1   = (const float*)d_in[2];
    const float* W2   = (const float*)d_in[3];
    const float* b2   = (const float*)d_in[4];
    const float* Wg   = (const float*)d_in[5];
    const float* bg   = (const float*)d_in[6];
    const float* Wf   = (const float*)d_in[7];
    const float* bf   = (const float*)d_in[8];
    const int*   edge = (const int*)d_in[9];
    const int*   batch= (const int*)d_in[10];

    const int E = in_sizes[9] / 2;
    const int n = in_sizes[10];
    const int nb = (n + 1023) / 1024;

    int *counts, *rowptr, *cursor, *srcs, *bsums;
    float *dinv, *hw2, *poolcnt;
    __nv_bfloat16 *ah, *al, *h1h, *h1l, *w1h, *w1l, *w2h, *w2l;
    cudaGetSymbolAddress((void**)&counts, g_counts);
    cudaGetSymbolAddress((void**)&rowptr, g_rowptr);
    cudaGetSymbolAddress((void**)&cursor, g_cursor);
    cudaGetSymbolAddress((void**)&srcs,   g_srcs);
    cudaGetSymbolAddress((void**)&bsums,  g_bsums);
    cudaGetSymbolAddress((void**)&dinv,   g_dinv);
    cudaGetSymbolAddress((void**)&ah,     g_a_h);
    cudaGetSymbolAddress((void**)&al,     g_a_l);
    cudaGetSymbolAddress((void**)&h1h,    g_h1h);
    cudaGetSymbolAddress((void**)&h1l,    g_h1l);
    cudaGetSymbolAddress((void**)&hw2,    g_hw2);
    cudaGetSymbolAddress((void**)&w1h,    g_w1h);
    cudaGetSymbolAddress((void**)&w1l,    g_w1l);
    cudaGetSymbolAddress((void**)&w2h,    g_w2h);
    cudaGetSymbolAddress((void**)&w2l,    g_w2l);
    cudaGetSymbolAddress((void**)&poolcnt,g_pool);
    float* pool = poolcnt;
    float* cnt  = poolcnt + (size_t)B_GR * EMB_D;

    float* out = (float*)d_out;
    float* out_emb = out;
    float* out_gl  = out + (size_t)B_GR * EMB_D;
    float* out_fam = out_gl + (size_t)B_GR * G_GRP;

    const int* src = edge;
    const int* dst = edge + E;

    cudaFuncSetAttribute(gemm_mma_kernel<true>,
                         cudaFuncAttributeMaxDynamicSharedMemorySize, GEMM_SMEM);
    cudaFuncSetAttribute(gemm_mma_kernel<false>,
                         cudaFuncAttributeMaxDynamicSharedMemorySize, GEMM_SMEM);

    // ---- fused prologue: zero counts/pool + weight splits (independent) ----
    const int nb0 = (n + 255) / 256;
    const int nb1 = ((B_GR * EMB_D + B_GR) / 4 + 255) / 256;
    setup_kernel<<<nb0 + nb1 + 256, 256>>>(counts, (float4*)poolcnt,
                                           W1, w1h, w1l, W2, w2h, w2l,
                                           n, nb0, nb1);

    // ---- CSR build ----
    hist_kernel<<<(E / 4 + 255) / 256, 256>>>(dst, counts, E);
    scan_block_kernel<<<nb, 1024>>>(counts, rowptr, bsums, dinv, n);
    scan_sums_kernel<<<1, 1024>>>(bsums, nb);
    scan_add_kernel<<<nb, 1024>>>(rowptr, cursor, bsums, n);
    place_kernel<<<(E / 4 + 255) / 256, 256>>>(src, dst, cursor, srcs, E);

    // ---- layer 1: gather (fp32 acc -> bf16 hi/lo), then HMMA GEMM ----
    gather_split_kernel<<<(n + 7) / 8, 256>>>(x, ah, al, rowptr, counts, srcs, dinv, n);
    {
        dim3 grid((n + 127) / 128, 2);   // N = 256
        gemm_mma_kernel<true><<<grid, 256, GEMM_SMEM>>>(
            ah, al, w1h, w1l, b1, h1h, h1l, nullptr, n, F_IN, H_DIM);
    }

    // ---- layer 2: HMMA GEMM (fp32 out), then fused gather+pool ----
    {
        dim3 grid((n + 127) / 128, 1);   // N = 128, K = 256
        gemm_mma_kernel<false><<<grid, 256, GEMM_SMEM>>>(
            h1h, h1l, w2h, w2l, nullptr, nullptr, nullptr, hw2, n, H_DIM, EMB_D);
    }
    gather_pool_kernel<<<(n + 7) / 8, 256>>>(hw2, rowptr, counts, srcs, dinv,
                                             batch, pool, cnt, n);

    // ---- heads (fam zeros folded in) ----
    head_kernel<<<B_GR, 128>>>(b2, Wg, bg, Wf, bf, pool, cnt,
                               out_emb, out_gl, out_fam);
}